// round 6
// baseline (speedup 1.0000x reference)
#include <cuda_runtime.h>
#include <cstddef>
#include <cstdint>

#define Bz 32
#define Tt 4096
#define Uu 512

// 256MB scratch: holds XW = x@w_x + b_h, overwritten in place by H during scan.
__device__ float g_xw[(size_t)Bz * Tt * Uu];
// per-group monotonic counters (8 groups, 128B apart)
__device__ unsigned int g_ctr[8 * 32];

// ---------------------------------------------------------------------------
__device__ __forceinline__ float my_tanh(float x) {
    float ax = fabsf(x);
    if (ax < 0.125f) {
        float x2 = x * x;
        return x * (1.f + x2 * (-0.333333333f + x2 * 0.133333333f));
    }
    float e = __expf(2.f * ax);
    float r = 1.f - 2.f / (1.f + e);
    return copysignf(r, x);
}

// ---------------------------------------------------------------------------
// SGEMM with bias: C[M,512] = A[M,512] @ B[512,512] + bias[512]
// 128x128 tile, BK=16, 256 threads, 8x8 per thread.
// Optional: counter reset (stream-ordered ahead of the scan kernel).
// ---------------------------------------------------------------------------
__global__ __launch_bounds__(256) void sgemm_bias(
    const float* __restrict__ A, const float* __restrict__ Bm,
    const float* __restrict__ bias, float* __restrict__ C,
    unsigned int* __restrict__ rctr)
{
    __shared__ float As[16][132];
    __shared__ float Bs[16][128];
    const int tid = threadIdx.x;
    const int tx = tid & 15, ty = tid >> 4;
    const size_t row0 = (size_t)blockIdx.y * 128;
    const int col0 = blockIdx.x * 128;

    if (rctr && blockIdx.x == 0 && blockIdx.y == 0 && tid < 8)
        rctr[tid * 32] = 0u;

    float acc[8][8];
#pragma unroll
    for (int i = 0; i < 8; i++)
#pragma unroll
        for (int j = 0; j < 8; j++) acc[i][j] = 0.f;

    for (int k0 = 0; k0 < 512; k0 += 16) {
#pragma unroll
        for (int l = 0; l < 2; l++) {
            int f = tid + l * 256;
            int ar = f >> 2, ak = (f & 3) << 2;
            float4 av = *(const float4*)&A[(row0 + ar) * 512 + k0 + ak];
            As[ak + 0][ar] = av.x;
            As[ak + 1][ar] = av.y;
            As[ak + 2][ar] = av.z;
            As[ak + 3][ar] = av.w;
            int br = f >> 5, bc = (f & 31) << 2;
            *(float4*)&Bs[br][bc] =
                *(const float4*)&Bm[(size_t)(k0 + br) * 512 + col0 + bc];
        }
        __syncthreads();
#pragma unroll
        for (int k = 0; k < 16; k++) {
            float a[8], b[8];
            *(float4*)&a[0] = *(const float4*)&As[k][ty * 8];
            *(float4*)&a[4] = *(const float4*)&As[k][ty * 8 + 4];
            *(float4*)&b[0] = *(const float4*)&Bs[k][tx * 8];
            *(float4*)&b[4] = *(const float4*)&Bs[k][tx * 8 + 4];
#pragma unroll
            for (int i = 0; i < 8; i++)
#pragma unroll
                for (int j = 0; j < 8; j++)
                    acc[i][j] = fmaf(a[i], b[j], acc[i][j]);
        }
        __syncthreads();
    }

    float bj[8];
    *(float4*)&bj[0] = *(const float4*)&bias[col0 + tx * 8];
    *(float4*)&bj[4] = *(const float4*)&bias[col0 + tx * 8 + 4];
#pragma unroll
    for (int i = 0; i < 8; i++) {
        size_t r = row0 + ty * 8 + i;
        float4 v0 = make_float4(acc[i][0] + bj[0], acc[i][1] + bj[1],
                                acc[i][2] + bj[2], acc[i][3] + bj[3]);
        float4 v1 = make_float4(acc[i][4] + bj[4], acc[i][5] + bj[5],
                                acc[i][6] + bj[6], acc[i][7] + bj[7]);
        *(float4*)&C[r * 512 + col0 + tx * 8] = v0;
        *(float4*)&C[r * 512 + col0 + tx * 8 + 4] = v1;
    }
}

// ---------------------------------------------------------------------------
// Recurrent scan v5. 8 groups x 16 CTAs, 512 threads/CTA.
// Group g owns batches [4g,4g+4); CTA c owns units [32c,32c+32).
// Thread = (k, q): k = output (unit uo=k>>2, batch bb=k&3), q = 128-d quarter.
// Each thread: 128-d partial dot; reduce = 2 shfl_xor; q==0 writes tanh.
// SMEM: w rows (uo*4+q) stride 132; h rows (bb*4+q) stride 132.
// Sync: one red.release.gpu.add per CTA + tid0 acquire-poll of group counter.
// ---------------------------------------------------------------------------
__global__ __launch_bounds__(512, 1) void rnn_scan5(
    const float* __restrict__ w_h, const float* __restrict__ h0)
{
    extern __shared__ float smem[];
    float* w_s = smem;                 // 128 rows * 132 = 16896 floats
    float* h_s = smem + 128 * 132;     // 16 rows * 132  =  2112 floats

    const int tid = threadIdx.x;
    const int grp = blockIdx.x >> 4;   // 0..7
    const int cig = blockIdx.x & 15;   // 0..15
    const int b0 = grp << 2;
    const int u0 = cig << 5;

    const int k  = tid >> 2;           // 0..127 output index
    const int q  = tid & 3;            // 0..3 d-quarter
    const int uo = k >> 2;             // 0..31 unit
    const int bb = k & 3;              // 0..3 batch

    // ---- load w slice: w_s[(uo*4 + d>>7)*132 + (d&127)] = w_h[d*512+u0+uo]
    for (int i = tid; i < 16384; i += 512) {
        int d = i >> 5, u = i & 31;
        w_s[(u * 4 + (d >> 7)) * 132 + (d & 127)] = w_h[d * 512 + u0 + u];
    }

    // ---- init h_{-1} = h0 (broadcast over 4 batches): one float4/thread
    {
        int b = tid >> 7, d4 = tid & 127;
        float4 v = *(const float4*)&h0[d4 * 4];
        *(float4*)&h_s[(b * 4 + (d4 >> 5)) * 132 + (d4 & 31) * 4] = v;
    }

    const float4* wrow = (const float4*)&w_s[(uo * 4 + q) * 132];
    const float4* hrow = (const float4*)&h_s[(bb * 4 + q) * 132];
    unsigned int* ctr = &g_ctr[grp * 32];

    // writer threads (q==0): own output slot + xw prefetch
    size_t oidx = 0;
    float xw_pf = 0.f;
    if (q == 0) {
        oidx = (size_t)(b0 + bb) * Tt * Uu + u0 + uo;
        xw_pf = __ldcg(&g_xw[oidx]);     // xw for t=0 (L2 only)
    }
    __syncthreads();

    for (int t = 0; t < Tt; t++) {
        // ---- 128-d partial dot (32 float4 iters) ----
        float4 a = make_float4(0.f, 0.f, 0.f, 0.f);
#pragma unroll
        for (int i = 0; i < 32; i++) {
            float4 w = wrow[i];
            float4 h = hrow[i];
            a.x = fmaf(w.x, h.x, a.x);
            a.y = fmaf(w.y, h.y, a.y);
            a.z = fmaf(w.z, h.z, a.z);
            a.w = fmaf(w.w, h.w, a.w);
        }
        float s = (a.x + a.y) + (a.z + a.w);
        s += __shfl_xor_sync(0xffffffffu, s, 1);
        s += __shfl_xor_sync(0xffffffffu, s, 2);

        // ---- writer: tanh, persist h_t, prefetch next xw ----
        if (q == 0) {
            float val = my_tanh(s + xw_pf);
            g_xw[oidx + (size_t)t * Uu] = val;
            if (t + 1 < Tt)
                xw_pf = __ldcg(&g_xw[oidx + (size_t)(t + 1) * Uu]);
        }
        __syncthreads();                 // all h stores of this CTA issued

        // ---- release + poll single group counter (no fence/IVALL) ----
        if (tid == 0) {
            asm volatile("red.release.gpu.global.add.u32 [%0], %1;"
                         :: "l"(ctr), "r"(1u) : "memory");
            unsigned int target = (unsigned int)(16 * (t + 1));
            unsigned int v;
            do {
                asm volatile("ld.acquire.gpu.global.u32 %0, [%1];"
                             : "=r"(v) : "l"(ctr));
            } while (v < target);
        }
        __syncthreads();

        // ---- load h_t (one float4 per thread, L2) ----
        if (t + 1 < Tt) {
            int b = tid >> 7, d4 = tid & 127;
            float4 v = __ldg((const float4*)&g_xw[
                ((size_t)(b0 + b) * Tt + t) * Uu + d4 * 4]);
            // single-touch addresses: L1 never stale, but use ldcg-equivalent
            *(float4*)&h_s[(b * 4 + (d4 >> 5)) * 132 + (d4 & 31) * 4] = v;
            __syncthreads();
        }
    }
}

// ---------------------------------------------------------------------------
// h_final = H[:, T-1, :]  (H itself, NOT its w_y projection)
__global__ void copy_hfinal(float* __restrict__ out) {
    int i = blockIdx.x * 256 + threadIdx.x;
    if (i < Bz * Uu) {
        int b = i >> 9, u = i & 511;
        out[(size_t)Bz * Tt * Uu + i] =
            g_xw[((size_t)b * Tt + (Tt - 1)) * Uu + u];
    }
}

// ---------------------------------------------------------------------------
extern "C" void kernel_launch(void* const* d_in, const int* in_sizes, int n_in,
                              void* d_out, int out_size) {
    const float* x   = (const float*)d_in[0];
    const float* w_h = (const float*)d_in[1];
    const float* w_x = (const float*)d_in[2];
    const float* w_y = (const float*)d_in[3];
    const float* b_h = (const float*)d_in[4];
    const float* b_y = (const float*)d_in[5];
    const float* h0  = (const float*)d_in[6];
    float* out = (float*)d_out;

    float* xw = nullptr;
    unsigned int* ctr = nullptr;
    cudaGetSymbolAddress((void**)&xw, g_xw);
    cudaGetSymbolAddress((void**)&ctr, g_ctr);
    const int smem_scan = (128 * 132 + 16 * 132) * 4;   // 76032 B
    cudaFuncSetAttribute(rnn_scan5, cudaFuncAttributeMaxDynamicSharedMemorySize,
                         smem_scan);

    dim3 gg(4, 1024);

    // Phase 1: XW = x @ w_x + b_h  (also resets scan counters)
    sgemm_bias<<<gg, 256>>>(x, w_x, b_h, xw, ctr);
    // Phase 2: sequential scan, H overwrites XW in place
    rnn_scan5<<<128, 512, smem_scan>>>(w_h, h0);
    // Phase 3: Y = H @ w_y + b_y
    sgemm_bias<<<gg, 256>>>(xw, w_y, b_y, out, nullptr);
    // h_final = H[:, T-1, :]
    copy_hfinal<<<64, 256>>>(out);
}

// round 8
// speedup vs baseline: 1.4058x; 1.4058x over previous
#include <cuda_runtime.h>
#include <cstddef>
#include <cstdint>

#define Bz 32
#define Tt 4096
#define Uu 512

// 256MB scratch: holds XW = x@w_x + b_h, overwritten in place by H during scan.
__device__ float g_xw[(size_t)Bz * Tt * Uu];
// per-group monotonic counters (8 groups, 128B apart)
__device__ unsigned int g_ctr[8 * 32];

// ---------------------------------------------------------------------------
__device__ __forceinline__ float my_tanh(float x) {
    float ax = fabsf(x);
    if (ax < 0.125f) {
        float x2 = x * x;
        return x * (1.f + x2 * (-0.333333333f + x2 * 0.133333333f));
    }
    float e = __expf(2.f * ax);
    float r = 1.f - 2.f / (1.f + e);
    return copysignf(r, x);
}

// ---------------------------------------------------------------------------
// SGEMM with bias: C[M,512] = A[M,512] @ B[512,512] + bias[512]
// 128x128 tile, BK=16, 256 threads, 8x8 per thread.
// Optional: counter reset (stream-ordered ahead of the scan kernel).
// ---------------------------------------------------------------------------
__global__ __launch_bounds__(256) void sgemm_bias(
    const float* __restrict__ A, const float* __restrict__ Bm,
    const float* __restrict__ bias, float* __restrict__ C,
    unsigned int* __restrict__ rctr)
{
    __shared__ float As[16][132];
    __shared__ float Bs[16][128];
    const int tid = threadIdx.x;
    const int tx = tid & 15, ty = tid >> 4;
    const size_t row0 = (size_t)blockIdx.y * 128;
    const int col0 = blockIdx.x * 128;

    if (rctr && blockIdx.x == 0 && blockIdx.y == 0 && tid < 8)
        rctr[tid * 32] = 0u;

    float acc[8][8];
#pragma unroll
    for (int i = 0; i < 8; i++)
#pragma unroll
        for (int j = 0; j < 8; j++) acc[i][j] = 0.f;

    for (int k0 = 0; k0 < 512; k0 += 16) {
#pragma unroll
        for (int l = 0; l < 2; l++) {
            int f = tid + l * 256;
            int ar = f >> 2, ak = (f & 3) << 2;
            float4 av = *(const float4*)&A[(row0 + ar) * 512 + k0 + ak];
            As[ak + 0][ar] = av.x;
            As[ak + 1][ar] = av.y;
            As[ak + 2][ar] = av.z;
            As[ak + 3][ar] = av.w;
            int br = f >> 5, bc = (f & 31) << 2;
            *(float4*)&Bs[br][bc] =
                *(const float4*)&Bm[(size_t)(k0 + br) * 512 + col0 + bc];
        }
        __syncthreads();
#pragma unroll
        for (int k = 0; k < 16; k++) {
            float a[8], b[8];
            *(float4*)&a[0] = *(const float4*)&As[k][ty * 8];
            *(float4*)&a[4] = *(const float4*)&As[k][ty * 8 + 4];
            *(float4*)&b[0] = *(const float4*)&Bs[k][tx * 8];
            *(float4*)&b[4] = *(const float4*)&Bs[k][tx * 8 + 4];
#pragma unroll
            for (int i = 0; i < 8; i++)
#pragma unroll
                for (int j = 0; j < 8; j++)
                    acc[i][j] = fmaf(a[i], b[j], acc[i][j]);
        }
        __syncthreads();
    }

    float bj[8];
    *(float4*)&bj[0] = *(const float4*)&bias[col0 + tx * 8];
    *(float4*)&bj[4] = *(const float4*)&bias[col0 + tx * 8 + 4];
#pragma unroll
    for (int i = 0; i < 8; i++) {
        size_t r = row0 + ty * 8 + i;
        float4 v0 = make_float4(acc[i][0] + bj[0], acc[i][1] + bj[1],
                                acc[i][2] + bj[2], acc[i][3] + bj[3]);
        float4 v1 = make_float4(acc[i][4] + bj[4], acc[i][5] + bj[5],
                                acc[i][6] + bj[6], acc[i][7] + bj[7]);
        *(float4*)&C[r * 512 + col0 + tx * 8] = v0;
        *(float4*)&C[r * 512 + col0 + tx * 8 + 4] = v1;
    }
}

// ---------------------------------------------------------------------------
// Recurrent scan v6. 8 groups x 16 CTAs, 256 threads/CTA.
// Group g owns batches [4g,4g+4); CTA c owns units [32c,32c+32).
// Warp w owns units 4w..4w+3 (w_h slice REGISTER-resident: 16 float4/thread).
// Lane = 16-d chunk. Per step each thread LDS-reads only 64 h floats (256B)
// -> 64KB/CTA/step crossbar (512cyc) hidden under the 1024cyc FMA phase.
// Reduce: shfl bits 3,4 -> psum (stride 18, conflict-free) -> 8-add.
// Barrier: R1's measured-best fence + atomicAdd + acquire spin.
// ---------------------------------------------------------------------------
__global__ __launch_bounds__(256, 1) void rnn_scan6(
    const float* __restrict__ w_h, const float* __restrict__ h0)
{
    extern __shared__ float smem[];
    float* w_s  = smem;                    // staging: 512*32 = 16384 floats
    float* h_s  = smem + 16384;            // 4*512 = 2048 floats
    float* psum = smem + 16384 + 2048;     // 8 warps * 8 lanes * 18 = 1152

    const int tid  = threadIdx.x;
    const int lane = tid & 31;
    const int warp = tid >> 5;
    const int grp  = blockIdx.x >> 4;      // 0..7
    const int cig  = blockIdx.x & 15;      // 0..15
    const int b0   = grp << 2;
    const int u0   = cig << 5;

    // ---- stage w slice (coalesced): w_s[d*32+j] = w_h[d*512 + u0 + j] ----
    for (int i = tid; i < 16384; i += 256) {
        int d = i >> 5, j = i & 31;
        w_s[i] = w_h[d * 512 + u0 + j];
    }
    __syncthreads();

    // ---- each thread pulls its 16x4 w block into registers ----
    // wq[d'] = (units 4*warp..4*warp+3) at global-d = lane*16 + d'
    float4 wq[16];
#pragma unroll
    for (int dp = 0; dp < 16; dp++) {
        int d = lane * 16 + dp;
        wq[dp] = make_float4(w_s[d * 32 + 4 * warp + 0],
                             w_s[d * 32 + 4 * warp + 1],
                             w_s[d * 32 + 4 * warp + 2],
                             w_s[d * 32 + 4 * warp + 3]);
    }

    // ---- init h_{-1} = h0 broadcast over 4 batches ----
    for (int i = tid; i < 2048; i += 256) h_s[i] = h0[i & 511];

    const float4* h_s4 = (const float4*)h_s;
    float4* h_s4w = (float4*)h_s;
    unsigned int* ctr = &g_ctr[grp * 32];

    // writer threads (tid < 128): output slot + xw prefetch
    size_t oidx = 0;
    float xw_pf = 0.f;
    if (tid < 128) {
        int wo = tid >> 4, z = tid & 15;
        int ul = 4 * wo + (z >> 2);        // unit within CTA
        int bb = z & 3;                    // batch within group
        oidx = (size_t)(b0 + bb) * Tt * Uu + u0 + ul;
        xw_pf = __ldcg(&g_xw[oidx]);       // xw for t=0 (L2 only)
    }
    __syncthreads();

    for (int t = 0; t < Tt; t++) {
        // ---- FMA phase: 16 d x 4 units x 4 batches per thread ----
        float acc[4][4];                   // [j(unit)][b]
#pragma unroll
        for (int j = 0; j < 4; j++)
#pragma unroll
            for (int b = 0; b < 4; b++) acc[j][b] = 0.f;

#pragma unroll
        for (int qd = 0; qd < 4; qd++) {
            float4 hv0 = h_s4[0 * 128 + lane * 4 + qd];
            float4 hv1 = h_s4[1 * 128 + lane * 4 + qd];
            float4 hv2 = h_s4[2 * 128 + lane * 4 + qd];
            float4 hv3 = h_s4[3 * 128 + lane * 4 + qd];
#pragma unroll
            for (int dd = 0; dd < 4; dd++) {
                float4 wv = wq[qd * 4 + dd];
                float hb0 = (&hv0.x)[dd];
                float hb1 = (&hv1.x)[dd];
                float hb2 = (&hv2.x)[dd];
                float hb3 = (&hv3.x)[dd];
                acc[0][0] = fmaf(wv.x, hb0, acc[0][0]);
                acc[1][0] = fmaf(wv.y, hb0, acc[1][0]);
                acc[2][0] = fmaf(wv.z, hb0, acc[2][0]);
                acc[3][0] = fmaf(wv.w, hb0, acc[3][0]);
                acc[0][1] = fmaf(wv.x, hb1, acc[0][1]);
                acc[1][1] = fmaf(wv.y, hb1, acc[1][1]);
                acc[2][1] = fmaf(wv.z, hb1, acc[2][1]);
                acc[3][1] = fmaf(wv.w, hb1, acc[3][1]);
                acc[0][2] = fmaf(wv.x, hb2, acc[0][2]);
                acc[1][2] = fmaf(wv.y, hb2, acc[1][2]);
                acc[2][2] = fmaf(wv.z, hb2, acc[2][2]);
                acc[3][2] = fmaf(wv.w, hb2, acc[3][2]);
                acc[0][3] = fmaf(wv.x, hb3, acc[0][3]);
                acc[1][3] = fmaf(wv.y, hb3, acc[1][3]);
                acc[2][3] = fmaf(wv.z, hb3, acc[2][3]);
                acc[3][3] = fmaf(wv.w, hb3, acc[3][3]);
            }
        }

        // ---- reduce over lane bits 3,4 -> lanes 0..7 hold partials ----
#pragma unroll
        for (int j = 0; j < 4; j++)
#pragma unroll
            for (int b = 0; b < 4; b++) {
                float s = acc[j][b];
                s += __shfl_xor_sync(0xffffffffu, s, 8);
                s += __shfl_xor_sync(0xffffffffu, s, 16);
                acc[j][b] = s;
            }
        if (lane < 8) {
            float* pr = &psum[(warp * 8 + lane) * 18];
#pragma unroll
            for (int j = 0; j < 4; j++)
#pragma unroll
                for (int b = 0; b < 4; b++) pr[j * 4 + b] = acc[j][b];
        }
        __syncthreads();

        // ---- final reduce (8 partials), tanh, persist h_t, prefetch xw ----
        if (tid < 128) {
            int wo = tid >> 4, z = tid & 15;
            float s = 0.f;
#pragma unroll
            for (int p = 0; p < 8; p++) s += psum[(wo * 8 + p) * 18 + z];
            float val = my_tanh(s + xw_pf);
            g_xw[oidx + (size_t)t * Uu] = val;
            if (t + 1 < Tt)
                xw_pf = __ldcg(&g_xw[oidx + (size_t)(t + 1) * Uu]);
        }
        __syncthreads();                   // CTA's h stores all issued

        // ---- R1 barrier: fence + atomic + acquire spin ----
        if (tid == 0) {
            __threadfence();
            atomicAdd(ctr, 1u);
            unsigned int target = (unsigned int)(16 * (t + 1));
            unsigned int v;
            do {
                asm volatile("ld.global.acquire.gpu.u32 %0, [%1];"
                             : "=r"(v) : "l"(ctr));
            } while (v < target);
        }
        __syncthreads();

        // ---- reload h_t (2 float4 per thread, L2) ----
        if (t + 1 < Tt) {
#pragma unroll
            for (int r = 0; r < 2; r++) {
                int idx = tid + r * 256;
                int b = idx >> 7, d4 = idx & 127;
                h_s4w[b * 128 + d4] = __ldcg((const float4*)&g_xw[
                    ((size_t)(b0 + b) * Tt + t) * Uu + d4 * 4]);
            }
            __syncthreads();
        }
    }
}

// ---------------------------------------------------------------------------
// h_final = H[:, T-1, :]  (H itself, NOT its w_y projection)
__global__ void copy_hfinal(float* __restrict__ out) {
    int i = blockIdx.x * 256 + threadIdx.x;
    if (i < Bz * Uu) {
        int b = i >> 9, u = i & 511;
        out[(size_t)Bz * Tt * Uu + i] =
            g_xw[((size_t)b * Tt + (Tt - 1)) * Uu + u];
    }
}

// ---------------------------------------------------------------------------
extern "C" void kernel_launch(void* const* d_in, const int* in_sizes, int n_in,
                              void* d_out, int out_size) {
    const float* x   = (const float*)d_in[0];
    const float* w_h = (const float*)d_in[1];
    const float* w_x = (const float*)d_in[2];
    const float* w_y = (const float*)d_in[3];
    const float* b_h = (const float*)d_in[4];
    const float* b_y = (const float*)d_in[5];
    const float* h0  = (const float*)d_in[6];
    float* out = (float*)d_out;

    float* xw = nullptr;
    unsigned int* ctr = nullptr;
    cudaGetSymbolAddress((void**)&xw, g_xw);
    cudaGetSymbolAddress((void**)&ctr, g_ctr);
    const int smem_scan = (16384 + 2048 + 1152) * 4;   // 78336 B
    cudaFuncSetAttribute(rnn_scan6, cudaFuncAttributeMaxDynamicSharedMemorySize,
                         smem_scan);

    dim3 gg(4, 1024);

    // Phase 1: XW = x @ w_x + b_h  (also resets scan counters)
    sgemm_bias<<<gg, 256>>>(x, w_x, b_h, xw, ctr);
    // Phase 2: sequential scan, H overwrites XW in place
    rnn_scan6<<<128, 256, smem_scan>>>(w_h, h0);
    // Phase 3: Y = H @ w_y + b_y
    sgemm_bias<<<gg, 256>>>(xw, w_y, b_y, out, nullptr);
    // h_final = H[:, T-1, :]
    copy_hfinal<<<64, 256>>>(out);
}

// round 9
// speedup vs baseline: 2.2690x; 1.6140x over previous
#include <cuda_runtime.h>
#include <cstddef>
#include <cstdint>

#define Bz 32
#define Tt 4096
#define Uu 512

// 256MB scratch: holds XW = x@w_x + b_h, overwritten in place by H during scan.
__device__ float g_xw[(size_t)Bz * Tt * Uu];
// per-group monotonic counters (8 groups, 128B apart)
__device__ unsigned int g_ctr[8 * 32];

// ---------------------------------------------------------------------------
__device__ __forceinline__ float my_tanh(float x) {
    float ax = fabsf(x);
    if (ax < 0.125f) {
        float x2 = x * x;
        return x * (1.f + x2 * (-0.333333333f + x2 * 0.133333333f));
    }
    float e = __expf(2.f * ax);
    float r = 1.f - 2.f / (1.f + e);
    return copysignf(r, x);
}

// ---------------------------------------------------------------------------
// SGEMM with bias: C[M,512] = A[M,512] @ B[512,512] + bias[512]
// 128x128 tile, BK=16, 256 threads, 8x8 per thread.
// Optional: counter reset (stream-ordered ahead of the scan kernel).
// ---------------------------------------------------------------------------
__global__ __launch_bounds__(256) void sgemm_bias(
    const float* __restrict__ A, const float* __restrict__ Bm,
    const float* __restrict__ bias, float* __restrict__ C,
    unsigned int* __restrict__ rctr)
{
    __shared__ float As[16][132];
    __shared__ float Bs[16][128];
    const int tid = threadIdx.x;
    const int tx = tid & 15, ty = tid >> 4;
    const size_t row0 = (size_t)blockIdx.y * 128;
    const int col0 = blockIdx.x * 128;

    if (rctr && blockIdx.x == 0 && blockIdx.y == 0 && tid < 8)
        rctr[tid * 32] = 0u;

    float acc[8][8];
#pragma unroll
    for (int i = 0; i < 8; i++)
#pragma unroll
        for (int j = 0; j < 8; j++) acc[i][j] = 0.f;

    for (int k0 = 0; k0 < 512; k0 += 16) {
#pragma unroll
        for (int l = 0; l < 2; l++) {
            int f = tid + l * 256;
            int ar = f >> 2, ak = (f & 3) << 2;
            float4 av = *(const float4*)&A[(row0 + ar) * 512 + k0 + ak];
            As[ak + 0][ar] = av.x;
            As[ak + 1][ar] = av.y;
            As[ak + 2][ar] = av.z;
            As[ak + 3][ar] = av.w;
            int br = f >> 5, bc = (f & 31) << 2;
            *(float4*)&Bs[br][bc] =
                *(const float4*)&Bm[(size_t)(k0 + br) * 512 + col0 + bc];
        }
        __syncthreads();
#pragma unroll
        for (int k = 0; k < 16; k++) {
            float a[8], b[8];
            *(float4*)&a[0] = *(const float4*)&As[k][ty * 8];
            *(float4*)&a[4] = *(const float4*)&As[k][ty * 8 + 4];
            *(float4*)&b[0] = *(const float4*)&Bs[k][tx * 8];
            *(float4*)&b[4] = *(const float4*)&Bs[k][tx * 8 + 4];
#pragma unroll
            for (int i = 0; i < 8; i++)
#pragma unroll
                for (int j = 0; j < 8; j++)
                    acc[i][j] = fmaf(a[i], b[j], acc[i][j]);
        }
        __syncthreads();
    }

    float bj[8];
    *(float4*)&bj[0] = *(const float4*)&bias[col0 + tx * 8];
    *(float4*)&bj[4] = *(const float4*)&bias[col0 + tx * 8 + 4];
#pragma unroll
    for (int i = 0; i < 8; i++) {
        size_t r = row0 + ty * 8 + i;
        float4 v0 = make_float4(acc[i][0] + bj[0], acc[i][1] + bj[1],
                                acc[i][2] + bj[2], acc[i][3] + bj[3]);
        float4 v1 = make_float4(acc[i][4] + bj[4], acc[i][5] + bj[5],
                                acc[i][6] + bj[6], acc[i][7] + bj[7]);
        *(float4*)&C[r * 512 + col0 + tx * 8] = v0;
        *(float4*)&C[r * 512 + col0 + tx * 8 + 4] = v1;
    }
}

// ---------------------------------------------------------------------------
// Recurrent scan v7 = R1's measured-best scan, verbatim, plus ONE change:
// xw kept in a register and the NEXT step's xw loaded right after the h
// store, so its memory latency hides under the fence+atomic+spin barrier.
// 8 groups x 16 CTAs. Group g owns batches [4g, 4g+4).
// CTA c-in-group owns units [32c, 32c+32), w_h slice (512x32) in SMEM.
// ---------------------------------------------------------------------------
__global__ __launch_bounds__(256) void rnn_scan7(const float* __restrict__ w_h,
                                                 const float* __restrict__ h0)
{
    extern __shared__ float smem[];
    float* w_s  = smem;                  // 512*32 = 16384 floats (64KB)
    float* h_s  = smem + 16384;          // 4*512  = 2048 floats
    float* psum = smem + 16384 + 2048;   // 8*128  = 1024 floats

    const int tid = threadIdx.x;
    const int grp = blockIdx.x >> 4;     // 0..7
    const int cig = blockIdx.x & 15;     // 0..15
    const int b0 = grp << 2;
    const int u0 = cig << 5;

    // load w_h slice: w_s[d*32 + j] = w_h[d*512 + u0 + j]
    for (int i = tid; i < 16384; i += 256) {
        int d = i >> 5, j = i & 31;
        w_s[i] = w_h[d * 512 + u0 + j];
    }

    const int ut   = tid & 7;    // which 4-unit tile (units ut*4..ut*4+3)
    const int dcw  = tid >> 3;   // which 16-d chunk (0..31)
    const int lane = tid & 31;
    const int warp = tid >> 5;
    const int d0q  = dcw << 2;   // d-chunk start / 4
    const float4* w_s4 = (const float4*)w_s;   // [d*8 + ut]
    const float4* h_s4 = (const float4*)h_s;   // [b*128 + d4]
    unsigned int* ctr = &g_ctr[grp * 32];

    // writer threads (tid < 128): own output slot + xw register prefetch
    size_t oidx = 0;
    float xw_pf = 0.f;
    if (tid < 128) {
        int ul = tid >> 2, bq = tid & 3;
        oidx = ((size_t)(b0 + bq) * Tt) * Uu + u0 + ul;
        xw_pf = g_xw[oidx];              // xw for t = 0
    }

    __syncthreads();

    for (int t = 0; t < Tt; t++) {
        // ---- load h_{t-1} into SMEM (4 batches x 512) ----
        if (t == 0) {
            for (int i = tid; i < 2048; i += 256) h_s[i] = h0[i & 511];
        } else {
            for (int i = tid; i < 512; i += 256) {
                int b = i >> 7, d4 = i & 127;
                ((float4*)h_s)[i] =
                    *((const float4*)&g_xw[((size_t)(b0 + b) * Tt + (t - 1)) * Uu] + d4);
            }
        }
        __syncthreads();

        // ---- partial dot products: 4 units x 4 batches over 16 d ----
        float acc[16];
#pragma unroll
        for (int z = 0; z < 16; z++) acc[z] = 0.f;
#pragma unroll
        for (int i = 0; i < 4; i++) {
            float4 hv[4];
            hv[0] = h_s4[d0q + i];
            hv[1] = h_s4[128 + d0q + i];
            hv[2] = h_s4[256 + d0q + i];
            hv[3] = h_s4[384 + d0q + i];
#pragma unroll
            for (int j = 0; j < 4; j++) {
                float4 wv = w_s4[((d0q + i) * 4 + j) * 8 + ut];
                const float w0 = wv.x, w1 = wv.y, w2 = wv.z, w3 = wv.w;
#pragma unroll
                for (int b = 0; b < 4; b++) {
                    float hb = ((const float*)&hv[b])[j];
                    acc[b * 4 + 0] = fmaf(w0, hb, acc[b * 4 + 0]);
                    acc[b * 4 + 1] = fmaf(w1, hb, acc[b * 4 + 1]);
                    acc[b * 4 + 2] = fmaf(w2, hb, acc[b * 4 + 2]);
                    acc[b * 4 + 3] = fmaf(w3, hb, acc[b * 4 + 3]);
                }
            }
        }

        // ---- reduce over the 4 d-chunks within each warp (lane bits 3,4) ----
#pragma unroll
        for (int z = 0; z < 16; z++) {
            acc[z] += __shfl_xor_sync(0xffffffffu, acc[z], 8);
            acc[z] += __shfl_xor_sync(0xffffffffu, acc[z], 16);
        }
        if (lane < 8) {
#pragma unroll
            for (int uj = 0; uj < 4; uj++)
#pragma unroll
                for (int b = 0; b < 4; b++)
                    psum[warp * 128 + ((ut * 4 + uj) << 2) + b] = acc[b * 4 + uj];
        }
        __syncthreads();

        // ---- final reduce over 8 warps, tanh, write h_t in place over xw ----
        if (tid < 128) {
            float s = 0.f;
#pragma unroll
            for (int w = 0; w < 8; w++) s += psum[w * 128 + tid];
            float val = my_tanh(s + xw_pf);
            g_xw[oidx + (size_t)t * Uu] = val;
            if (t + 1 < Tt)   // prefetch next xw; latency hides under barrier
                xw_pf = g_xw[oidx + (size_t)(t + 1) * Uu];
        }
        __syncthreads();

        // ---- group barrier: release our stores, wait for the 16 CTAs ----
        if (tid == 0) {
            __threadfence();
            atomicAdd(ctr, 1u);
            unsigned int target = (unsigned int)(16 * (t + 1));
            unsigned int v;
            do {
                asm volatile("ld.global.acquire.gpu.u32 %0, [%1];"
                             : "=r"(v) : "l"(ctr));
            } while (v < target);
        }
        __syncthreads();
    }
}

// ---------------------------------------------------------------------------
// h_final = H[:, T-1, :]  (H itself, NOT its w_y projection)
__global__ void copy_hfinal(float* __restrict__ out) {
    int i = blockIdx.x * 256 + threadIdx.x;
    if (i < Bz * Uu) {
        int b = i >> 9, u = i & 511;
        out[(size_t)Bz * Tt * Uu + i] =
            g_xw[((size_t)b * Tt + (Tt - 1)) * Uu + u];
    }
}

// ---------------------------------------------------------------------------
extern "C" void kernel_launch(void* const* d_in, const int* in_sizes, int n_in,
                              void* d_out, int out_size) {
    const float* x   = (const float*)d_in[0];
    const float* w_h = (const float*)d_in[1];
    const float* w_x = (const float*)d_in[2];
    const float* w_y = (const float*)d_in[3];
    const float* b_h = (const float*)d_in[4];
    const float* b_y = (const float*)d_in[5];
    const float* h0  = (const float*)d_in[6];
    float* out = (float*)d_out;

    float* xw = nullptr;
    unsigned int* ctr = nullptr;
    cudaGetSymbolAddress((void**)&xw, g_xw);
    cudaGetSymbolAddress((void**)&ctr, g_ctr);
    const int smem_scan = (16384 + 2048 + 1024) * 4;
    cudaFuncSetAttribute(rnn_scan7, cudaFuncAttributeMaxDynamicSharedMemorySize,
                         smem_scan);

    dim3 gg(4, 1024);

    // Phase 1: XW = x @ w_x + b_h  (also resets scan counters)
    sgemm_bias<<<gg, 256>>>(x, w_x, b_h, xw, ctr);
    // Phase 2: sequential scan, H overwrites XW in place
    rnn_scan7<<<128, 256, smem_scan>>>(w_h, h0);
    // Phase 3: Y = H @ w_y + b_y
    sgemm_bias<<<gg, 256>>>(xw, w_y, b_y, out, nullptr);
    // h_final = H[:, T-1, :]
    copy_hfinal<<<64, 256>>>(out);
}